// round 15
// baseline (speedup 1.0000x reference)
#include <cuda_runtime.h>
#include <math.h>
#include <stdint.h>

#define D_MODEL 1024
#define N_RES   2048
#define BATCH   32
#define TWO_D   2048
#define TILE_G  16            // GEMM row tile (8 warps x 2 rows)
#define GCHUNK  128           // GEMM pipeline chunk (reduction axis)
#define RRANGE  512           // per-block reduction range
#define RCHUNKS (RRANGE / GCHUNK)   // 4
#define KSPLIT  4
#define NSPLIT  4
#define DSPLIT  8
#define CHUNK   128

// ---- scratch (device globals; no allocation allowed) ----
__device__ __align__(16) float g_xcombT[TWO_D * BATCH];                  // [k][b]
__device__ __align__(16) float g_xc_part[KSPLIT * D_MODEL * BATCH];      // [s][d][b]
__device__ __align__(16) float g_xcT  [D_MODEL * BATCH];                 // [d][b]
__device__ __align__(16) float g_cos_part[DSPLIT * N_RES * BATCH];       // [s][n][b]
__device__ __align__(16) float g_sin_part[DSPLIT * N_RES * BATCH];
__device__ __align__(16) float g_cosT [N_RES * BATCH];                   // rotated sums [n][b]
__device__ __align__(16) float g_sinT [N_RES * BATCH];
__device__ __align__(16) float g_out_part[NSPLIT * 2 * D_MODEL * BATCH]; // [s][row][b]

__device__ int g_cnt_proj[D_MODEL / TILE_G];           // 64
__device__ int g_cnt_res [N_RES / 8];                  // 256
__device__ int g_cnt_out [2 * (D_MODEL / TILE_G)];     // 128

#define CP_ASYNC16(dst_u32, src_ptr) \
    asm volatile("cp.async.cg.shared.global [%0], [%1], 16;" :: "r"(dst_u32), "l"(src_ptr))
#define CP_COMMIT() asm volatile("cp.async.commit_group;")
#define CP_WAIT(N)  asm volatile("cp.async.wait_group %0;" :: "n"(N))

// ---------------------------------------------------------------------------
// K0: transpose x -> xcombT via smem tiles (64 blocks, tiny).
// ---------------------------------------------------------------------------
__global__ void __launch_bounds__(256)
prep_kernel(const float* __restrict__ xr,
            const float* __restrict__ xi) {
    __shared__ float tile[32][33];
    const int k0   = blockIdx.x * 32;
    const int w    = threadIdx.x >> 5;
    const int lane = threadIdx.x & 31;
    #pragma unroll
    for (int bb = w; bb < 32; bb += 8) {
        int k = k0 + lane;
        float v = (k < D_MODEL) ? xr[bb * D_MODEL + k]
                                : xi[bb * D_MODEL + (k - D_MODEL)];
        tile[lane][bb] = v;
    }
    __syncthreads();
    #pragma unroll
    for (int kk = w; kk < 32; kk += 8)
        g_xcombT[(k0 + kk) * BATCH + lane] = tile[kk][lane];
}

// ---------------------------------------------------------------------------
// GEMM core: warp w owns rows 2w, 2w+1 over the full 512 reduction range.
// Weights cp.async double-buffered; src read via L1-broadcast LDG.
// No cross-warp reduction: acc[2] per thread.
// ---------------------------------------------------------------------------
__device__ __forceinline__ void gemm_pipeline(
    const float* __restrict__ wrow0,   // weight row base (row 0 of tile)
    size_t  wstride,                   // elements per weight row
    int     rbase,                     // reduction-range base (global)
    const float* __restrict__ src,     // [r][b] activations
    float   (&sbuf)[2][TILE_G * GCHUNK],
    float   acc[2],
    int     w, int lane, int tid)
{
    // prefetch chunk 0: 512 float4, 2 per thread
    #pragma unroll
    for (int p = 0; p < 2; p++) {
        int idx = p * 256 + tid;
        int r   = idx >> 5;                  // 0..15
        int c4  = (idx & 31) * 4;            // 0..124
        uint32_t dst = (uint32_t)__cvta_generic_to_shared(&sbuf[0][r * GCHUNK + c4]);
        CP_ASYNC16(dst, wrow0 + (size_t)r * wstride + rbase + c4);
    }
    CP_COMMIT();

    #pragma unroll
    for (int c = 0; c < RCHUNKS; c++) {
        if (c < RCHUNKS - 1) {
            #pragma unroll
            for (int p = 0; p < 2; p++) {
                int idx = p * 256 + tid;
                int r   = idx >> 5;
                int c4  = (idx & 31) * 4;
                uint32_t dst = (uint32_t)__cvta_generic_to_shared(&sbuf[(c + 1) & 1][r * GCHUNK + c4]);
                CP_ASYNC16(dst, wrow0 + (size_t)r * wstride + rbase + (c + 1) * GCHUNK + c4);
            }
            CP_COMMIT();
            CP_WAIT(1);
        } else {
            CP_WAIT(0);
        }
        __syncthreads();

        const float* w0 = &sbuf[c & 1][(2 * w) * GCHUNK];
        const float* w1 = w0 + GCHUNK;
        const float* sp = src + (size_t)(rbase + c * GCHUNK) * BATCH + lane;

        #pragma unroll 8
        for (int n = 0; n < GCHUNK; n += 4) {
            float s0 = sp[(n + 0) * BATCH];
            float s1 = sp[(n + 1) * BATCH];
            float s2 = sp[(n + 2) * BATCH];
            float s3 = sp[(n + 3) * BATCH];
            float4 a = *(const float4*)(w0 + n);
            float4 b = *(const float4*)(w1 + n);
            acc[0] = fmaf(s3, a.w, fmaf(s2, a.z, fmaf(s1, a.y, fmaf(s0, a.x, acc[0]))));
            acc[1] = fmaf(s3, b.w, fmaf(s2, b.z, fmaf(s1, b.y, fmaf(s0, b.x, acc[1]))));
        }
        __syncthreads();
    }
}

// ---------------------------------------------------------------------------
// K1: input projection. grid (64, KSPLIT=4). Last split-block combines + bias.
// ---------------------------------------------------------------------------
__global__ void __launch_bounds__(256)
proj_kernel(const float* __restrict__ ipw,
            const float* __restrict__ ipb) {
    __shared__ float sbuf[2][TILE_G * GCHUNK];   // 16 KB
    __shared__ int   s_last;

    const int dt    = blockIdx.x * TILE_G;
    const int kbase = blockIdx.y * RRANGE;
    const int w     = threadIdx.x >> 5;
    const int lane  = threadIdx.x & 31;

    float acc[2] = {0.f, 0.f};
    gemm_pipeline(ipw + (size_t)dt * TWO_D, TWO_D, kbase, g_xcombT,
                  sbuf, acc, w, lane, threadIdx.x);

    const int r0 = dt + 2 * w;
    g_xc_part[((size_t)blockIdx.y * D_MODEL + r0 + 0) * BATCH + lane] = acc[0];
    g_xc_part[((size_t)blockIdx.y * D_MODEL + r0 + 1) * BATCH + lane] = acc[1];

    __threadfence();
    if (threadIdx.x == 0) {
        int old = atomicAdd(&g_cnt_proj[blockIdx.x], 1);
        s_last = (old == KSPLIT - 1);
    }
    __syncthreads();
    if (s_last) {
        __threadfence();
        #pragma unroll
        for (int p = 0; p < 2; p++) {
            int row = r0 + p;
            float c = 0.f;
            #pragma unroll
            for (int sp = 0; sp < KSPLIT; sp++)
                c += g_xc_part[((size_t)sp * D_MODEL + row) * BATCH + lane];
            g_xcT[(size_t)row * BATCH + lane] = c + __ldg(ipb + row);
        }
        if (threadIdx.x == 0) g_cnt_proj[blockIdx.x] = 0;
    }
}

// ---------------------------------------------------------------------------
// K2: resonance, 8-way d-split; one 128-d chunk per block. (unchanged)
// ---------------------------------------------------------------------------
__global__ void __launch_bounds__(256, 6)
resonance_kernel(const float* __restrict__ Wmat,
                 const float* __restrict__ Bmat,
                 const float* __restrict__ t) {
    __shared__ float s_rw[8 * CHUNK];
    __shared__ float s_B [8 * CHUNK];
    __shared__ float s_xc[CHUNK * BATCH];
    __shared__ int   s_last;

    const int n0    = blockIdx.x * 8;
    const int split = blockIdx.y;
    const int c0    = split * CHUNK;
    const int w     = threadIdx.x >> 5;
    const int lane  = threadIdx.x & 31;

    {
        const int off = lane * 4;
        float4 w4 = __ldg((const float4*)(Wmat + (size_t)(n0 + w) * D_MODEL + c0 + off));
        float4 r;
        r.x = __fdividef(1.0f, 1.0f + fabsf(w4.x));
        r.y = __fdividef(1.0f, 1.0f + fabsf(w4.y));
        r.z = __fdividef(1.0f, 1.0f + fabsf(w4.z));
        r.w = __fdividef(1.0f, 1.0f + fabsf(w4.w));
        *(float4*)(s_rw + w * CHUNK + off) = r;
        *(float4*)(s_B + w * CHUNK + off) =
            __ldg((const float4*)(Bmat + (size_t)(n0 + w) * D_MODEL + c0 + off));
        const float4* src = (const float4*)(g_xcT + (size_t)c0 * BATCH);
        float4* dst = (float4*)s_xc;
        #pragma unroll
        for (int p = 0; p < 4; p++)
            dst[p * 256 + threadIdx.x] = src[p * 256 + threadIdx.x];
    }
    __syncthreads();

    float ca0 = 0.f, ca1 = 0.f, sa0 = 0.f, sa1 = 0.f;

    #pragma unroll 4
    for (int d = 0; d < CHUNK; d += 4) {
        float4 rw4 = *(const float4*)(s_rw + w * CHUNK + d);
        float4 b4  = *(const float4*)(s_B  + w * CHUNK + d);

        float xc0 = s_xc[(d + 0) * BATCH + lane];
        float xc1 = s_xc[(d + 1) * BATCH + lane];
        float xc2 = s_xc[(d + 2) * BATCH + lane];
        float xc3 = s_xc[(d + 3) * BATCH + lane];

        float th0 = fmaf(xc0, rw4.x, b4.x);
        float th1 = fmaf(xc1, rw4.y, b4.y);
        float th2 = fmaf(xc2, rw4.z, b4.z);
        float th3 = fmaf(xc3, rw4.w, b4.w);

        sa0 += __sinf(th0);  ca0 += __cosf(th0);
        sa1 += __sinf(th1);  ca1 += __cosf(th1);
        sa0 += __sinf(th2);  ca0 += __cosf(th2);
        sa1 += __sinf(th3);  ca1 += __cosf(th3);
    }
    g_cos_part[((size_t)split * N_RES + n0 + w) * BATCH + lane] = ca0 + ca1;
    g_sin_part[((size_t)split * N_RES + n0 + w) * BATCH + lane] = sa0 + sa1;

    __threadfence();
    if (threadIdx.x == 0) {
        int old = atomicAdd(&g_cnt_res[blockIdx.x], 1);
        s_last = (old == DSPLIT - 1);
    }
    __syncthreads();
    if (s_last) {
        __threadfence();
        const int n = n0 + w;
        float C = 0.f, S = 0.f;
        #pragma unroll
        for (int sp = 0; sp < DSPLIT; sp++) {
            C += g_cos_part[((size_t)sp * N_RES + n) * BATCH + lane];
            S += g_sin_part[((size_t)sp * N_RES + n) * BATCH + lane];
        }
        float st, ct;
        __sincosf(__ldg(t + lane), &st, &ct);
        g_cosT[(size_t)n * BATCH + lane] = fmaf(C, ct, -S * st);
        g_sinT[(size_t)n * BATCH + lane] = fmaf(S, ct,  C * st);
        if (threadIdx.x == 0) g_cnt_res[blockIdx.x] = 0;
    }
}

// ---------------------------------------------------------------------------
// K3: output projection. grid (64, NSPLIT=4, 2).
// Last split-block combines + silu + transposed store.
// ---------------------------------------------------------------------------
__global__ void __launch_bounds__(256)
outproj_kernel(const float* __restrict__ wr,
               const float* __restrict__ wi,
               float* __restrict__ out) {
    __shared__ float sbuf[2][TILE_G * GCHUNK];   // 16 KB
    __shared__ float tile[TILE_G][33];           // 2 KB
    __shared__ int   s_last;

    const int  dt      = blockIdx.x * TILE_G;
    const int  nbase   = blockIdx.y * RRANGE;
    const bool is_imag = blockIdx.z != 0;
    const int  w       = threadIdx.x >> 5;
    const int  lane    = threadIdx.x & 31;

    const float* wbase = is_imag ? wi : wr;
    const float* src   = is_imag ? g_sinT : g_cosT;

    float acc[2] = {0.f, 0.f};
    gemm_pipeline(wbase + (size_t)dt * N_RES, N_RES, nbase, src,
                  sbuf, acc, w, lane, threadIdx.x);

    const int r0  = dt + 2 * w;
    const int rowbase = (is_imag ? D_MODEL : 0);
    g_out_part[((size_t)blockIdx.y * 2 * D_MODEL + rowbase + r0 + 0) * BATCH + lane] = acc[0];
    g_out_part[((size_t)blockIdx.y * 2 * D_MODEL + rowbase + r0 + 1) * BATCH + lane] = acc[1];

    const int cidx = blockIdx.z * (D_MODEL / TILE_G) + blockIdx.x;
    __threadfence();
    if (threadIdx.x == 0) {
        int old = atomicAdd(&g_cnt_out[cidx], 1);
        s_last = (old == NSPLIT - 1);
    }
    __syncthreads();
    if (s_last) {
        __threadfence();
        #pragma unroll
        for (int p = 0; p < 2; p++) {
            int row = rowbase + r0 + p;
            float c = 0.f;
            #pragma unroll
            for (int sp = 0; sp < NSPLIT; sp++)
                c += g_out_part[((size_t)sp * 2 * D_MODEL + row) * BATCH + lane];
            tile[2 * w + p][lane] = c / (1.0f + __expf(-c));   // silu
        }
        __syncthreads();
        #pragma unroll
        for (int p = 0; p < 2; p++) {
            const int b  = threadIdx.x >> 3;
            const int dl = (threadIdx.x & 7) + p * 8;
            out[(is_imag ? BATCH * D_MODEL : 0) + (size_t)b * D_MODEL + dt + dl] = tile[dl][b];
        }
        if (threadIdx.x == 0) g_cnt_out[cidx] = 0;
    }
}

// ---------------------------------------------------------------------------
extern "C" void kernel_launch(void* const* d_in, const int* in_sizes, int n_in,
                              void* d_out, int out_size) {
    const float* x_real = (const float*)d_in[0];
    const float* x_imag = (const float*)d_in[1];
    const float* t      = (const float*)d_in[2];
    const float* ipw    = (const float*)d_in[3];
    const float* ipb    = (const float*)d_in[4];
    const float* W      = (const float*)d_in[5];
    const float* Bmat   = (const float*)d_in[6];
    const float* orw    = (const float*)d_in[7];
    const float* oiw    = (const float*)d_in[8];
    float* out = (float*)d_out;

    prep_kernel<<<64, 256>>>(x_real, x_imag);
    proj_kernel<<<dim3(D_MODEL / TILE_G, KSPLIT), 256>>>(ipw, ipb);
    resonance_kernel<<<dim3(N_RES / 8, DSPLIT), 256>>>(W, Bmat, t);
    outproj_kernel<<<dim3(D_MODEL / TILE_G, NSPLIT, 2), 256>>>(orw, oiw, out);
}

// round 16
// speedup vs baseline: 1.4770x; 1.4770x over previous
#include <cuda_runtime.h>
#include <math.h>
#include <stdint.h>

#define D_MODEL 1024
#define N_RES   2048
#define BATCH   32
#define TWO_D   2048
#define TILE_G  16            // GEMM row tile
#define GCHUNK  128           // GEMM pipeline chunk (reduction axis)
#define RRANGE  512           // per-block reduction range
#define RCHUNKS (RRANGE / GCHUNK)   // 4
#define NSTAGE  3             // cp.async pipeline depth
#define KSPLIT  4
#define NSPLIT  4
#define DSPLIT  8
#define CHUNK   128

// ---- scratch (device globals; no allocation allowed) ----
__device__ __align__(16) float g_xcombT[TWO_D * BATCH];                  // [k][b]
__device__ __align__(16) float g_xc_part[KSPLIT * D_MODEL * BATCH];      // [s][d][b]
__device__ __align__(16) float g_xcT  [D_MODEL * BATCH];                 // [d][b]
__device__ __align__(16) float g_cos_part[DSPLIT * N_RES * BATCH];       // [s][n][b]
__device__ __align__(16) float g_sin_part[DSPLIT * N_RES * BATCH];
__device__ __align__(16) float g_cosT [N_RES * BATCH];                   // rotated sums [n][b]
__device__ __align__(16) float g_sinT [N_RES * BATCH];
__device__ __align__(16) float g_out_part[NSPLIT * 2 * D_MODEL * BATCH]; // [s][row][b]

__device__ int g_cnt_proj[D_MODEL / TILE_G];           // 64
__device__ int g_cnt_res [N_RES / 8];                  // 256
__device__ int g_cnt_out [2 * (D_MODEL / TILE_G)];     // 128

#define CP_ASYNC16(dst_u32, src_ptr) \
    asm volatile("cp.async.cg.shared.global [%0], [%1], 16;" :: "r"(dst_u32), "l"(src_ptr))
#define CP_COMMIT() asm volatile("cp.async.commit_group;")
#define CP_WAIT(N)  asm volatile("cp.async.wait_group %0;" :: "n"(N))

// ---------------------------------------------------------------------------
// K0: transpose x -> xcombT via smem tiles (64 blocks, tiny).
// ---------------------------------------------------------------------------
__global__ void __launch_bounds__(256)
prep_kernel(const float* __restrict__ xr,
            const float* __restrict__ xi) {
    __shared__ float tile[32][33];
    const int k0   = blockIdx.x * 32;
    const int w    = threadIdx.x >> 5;
    const int lane = threadIdx.x & 31;
    #pragma unroll
    for (int bb = w; bb < 32; bb += 8) {
        int k = k0 + lane;
        float v = (k < D_MODEL) ? xr[bb * D_MODEL + k]
                                : xi[bb * D_MODEL + (k - D_MODEL)];
        tile[lane][bb] = v;
    }
    __syncthreads();
    #pragma unroll
    for (int kk = w; kk < 32; kk += 8)
        g_xcombT[(k0 + kk) * BATCH + lane] = tile[kk][lane];
}

// ---------------------------------------------------------------------------
// GEMM core: 16 rows x 512 reduction range, 4 chunks of 128,
// cp.async TRIPLE-buffered (2 chunks in flight). Warp w owns a 16-wide
// reduction-subslice per chunk; lane = batch.
// ---------------------------------------------------------------------------
__device__ __forceinline__ void prefetch_chunk(
    const float* __restrict__ wrow0, size_t wstride, int rbase,
    float* buf, int c, int tid)
{
    #pragma unroll
    for (int p = 0; p < 2; p++) {
        int idx = p * 256 + tid;             // 512 float4
        int r   = idx >> 5;                  // 0..15
        int c4  = (idx & 31) * 4;            // 0..124
        uint32_t dst = (uint32_t)__cvta_generic_to_shared(&buf[r * GCHUNK + c4]);
        CP_ASYNC16(dst, wrow0 + (size_t)r * wstride + rbase + c * GCHUNK + c4);
    }
    CP_COMMIT();
}

__device__ __forceinline__ void gemm_pipeline(
    const float* __restrict__ wrow0,   // weight row base (row 0 of tile)
    size_t  wstride,                   // elements per weight row
    int     rbase,                     // reduction-range base (global)
    const float* __restrict__ src,     // [r][b] activations
    float   (&sbuf)[NSTAGE][TILE_G * GCHUNK],
    float   acc[TILE_G],
    int     w, int lane, int tid)
{
    prefetch_chunk(wrow0, wstride, rbase, sbuf[0], 0, tid);
    prefetch_chunk(wrow0, wstride, rbase, sbuf[1], 1, tid);

    #pragma unroll
    for (int c = 0; c < RCHUNKS; c++) {
        if (c + 2 < RCHUNKS) {
            prefetch_chunk(wrow0, wstride, rbase, sbuf[(c + 2) % NSTAGE], c + 2, tid);
            CP_WAIT(2);
        } else if (c + 1 < RCHUNKS) {
            CP_WAIT(1);
        } else {
            CP_WAIT(0);
        }
        __syncthreads();

        const float* wc = sbuf[c % NSTAGE];
        #pragma unroll
        for (int i = 0; i < 4; i++) {
            int ln = w * 16 + i * 4;             // reduction idx within chunk
            int gn = rbase + c * GCHUNK + ln;    // global reduction idx
            float s0 = src[(size_t)(gn + 0) * BATCH + lane];
            float s1 = src[(size_t)(gn + 1) * BATCH + lane];
            float s2 = src[(size_t)(gn + 2) * BATCH + lane];
            float s3 = src[(size_t)(gn + 3) * BATCH + lane];
            #pragma unroll
            for (int r = 0; r < TILE_G; r++) {
                float4 w4 = *(const float4*)(wc + r * GCHUNK + ln);
                acc[r] = fmaf(s3, w4.w, fmaf(s2, w4.z, fmaf(s1, w4.y, fmaf(s0, w4.x, acc[r]))));
            }
        }
        __syncthreads();   // buffer safe for reuse
    }
}

// ---------------------------------------------------------------------------
// K1: input projection. grid (64, KSPLIT=4). Last split-block combines + bias.
// ---------------------------------------------------------------------------
__global__ void __launch_bounds__(256)
proj_kernel(const float* __restrict__ ipw,
            const float* __restrict__ ipb) {
    __shared__ float sbuf[NSTAGE][TILE_G * GCHUNK];   // 24 KB
    __shared__ float red[8][TILE_G][32];              // 16 KB
    __shared__ int   s_last;

    const int dt    = blockIdx.x * TILE_G;
    const int kbase = blockIdx.y * RRANGE;
    const int w     = threadIdx.x >> 5;
    const int lane  = threadIdx.x & 31;

    float acc[TILE_G];
    #pragma unroll
    for (int i = 0; i < TILE_G; i++) acc[i] = 0.f;

    gemm_pipeline(ipw + (size_t)dt * TWO_D, TWO_D, kbase, g_xcombT,
                  sbuf, acc, w, lane, threadIdx.x);

    #pragma unroll
    for (int i = 0; i < TILE_G; i++) red[w][i][lane] = acc[i];
    __syncthreads();

    #pragma unroll
    for (int p = 0; p < 2; p++) {
        int td = (threadIdx.x >> 5) + p * 8;
        float s = 0.f;
        #pragma unroll
        for (int ww = 0; ww < 8; ww++) s += red[ww][td][lane];
        g_xc_part[((size_t)blockIdx.y * D_MODEL + dt + td) * BATCH + lane] = s;
    }

    __threadfence();
    if (threadIdx.x == 0) {
        int old = atomicAdd(&g_cnt_proj[blockIdx.x], 1);
        s_last = (old == KSPLIT - 1);
    }
    __syncthreads();
    if (s_last) {
        __threadfence();
        #pragma unroll
        for (int p = 0; p < 2; p++) {
            int td = (threadIdx.x >> 5) + p * 8;
            float c = 0.f;
            #pragma unroll
            for (int sp = 0; sp < KSPLIT; sp++)
                c += g_xc_part[((size_t)sp * D_MODEL + dt + td) * BATCH + lane];
            g_xcT[(size_t)(dt + td) * BATCH + lane] = c + __ldg(ipb + dt + td);
        }
        if (threadIdx.x == 0) g_cnt_proj[blockIdx.x] = 0;
    }
}

// ---------------------------------------------------------------------------
// K2: resonance, 8-way d-split; one 128-d chunk per block. (unchanged)
// ---------------------------------------------------------------------------
__global__ void __launch_bounds__(256, 6)
resonance_kernel(const float* __restrict__ Wmat,
                 const float* __restrict__ Bmat,
                 const float* __restrict__ t) {
    __shared__ float s_rw[8 * CHUNK];
    __shared__ float s_B [8 * CHUNK];
    __shared__ float s_xc[CHUNK * BATCH];
    __shared__ int   s_last;

    const int n0    = blockIdx.x * 8;
    const int split = blockIdx.y;
    const int c0    = split * CHUNK;
    const int w     = threadIdx.x >> 5;
    const int lane  = threadIdx.x & 31;

    {
        const int off = lane * 4;
        float4 w4 = __ldg((const float4*)(Wmat + (size_t)(n0 + w) * D_MODEL + c0 + off));
        float4 r;
        r.x = __fdividef(1.0f, 1.0f + fabsf(w4.x));
        r.y = __fdividef(1.0f, 1.0f + fabsf(w4.y));
        r.z = __fdividef(1.0f, 1.0f + fabsf(w4.z));
        r.w = __fdividef(1.0f, 1.0f + fabsf(w4.w));
        *(float4*)(s_rw + w * CHUNK + off) = r;
        *(float4*)(s_B + w * CHUNK + off) =
            __ldg((const float4*)(Bmat + (size_t)(n0 + w) * D_MODEL + c0 + off));
        const float4* src = (const float4*)(g_xcT + (size_t)c0 * BATCH);
        float4* dst = (float4*)s_xc;
        #pragma unroll
        for (int p = 0; p < 4; p++)
            dst[p * 256 + threadIdx.x] = src[p * 256 + threadIdx.x];
    }
    __syncthreads();

    float ca0 = 0.f, ca1 = 0.f, sa0 = 0.f, sa1 = 0.f;

    #pragma unroll 4
    for (int d = 0; d < CHUNK; d += 4) {
        float4 rw4 = *(const float4*)(s_rw + w * CHUNK + d);
        float4 b4  = *(const float4*)(s_B  + w * CHUNK + d);

        float xc0 = s_xc[(d + 0) * BATCH + lane];
        float xc1 = s_xc[(d + 1) * BATCH + lane];
        float xc2 = s_xc[(d + 2) * BATCH + lane];
        float xc3 = s_xc[(d + 3) * BATCH + lane];

        float th0 = fmaf(xc0, rw4.x, b4.x);
        float th1 = fmaf(xc1, rw4.y, b4.y);
        float th2 = fmaf(xc2, rw4.z, b4.z);
        float th3 = fmaf(xc3, rw4.w, b4.w);

        sa0 += __sinf(th0);  ca0 += __cosf(th0);
        sa1 += __sinf(th1);  ca1 += __cosf(th1);
        sa0 += __sinf(th2);  ca0 += __cosf(th2);
        sa1 += __sinf(th3);  ca1 += __cosf(th3);
    }
    g_cos_part[((size_t)split * N_RES + n0 + w) * BATCH + lane] = ca0 + ca1;
    g_sin_part[((size_t)split * N_RES + n0 + w) * BATCH + lane] = sa0 + sa1;

    __threadfence();
    if (threadIdx.x == 0) {
        int old = atomicAdd(&g_cnt_res[blockIdx.x], 1);
        s_last = (old == DSPLIT - 1);
    }
    __syncthreads();
    if (s_last) {
        __threadfence();
        const int n = n0 + w;
        float C = 0.f, S = 0.f;
        #pragma unroll
        for (int sp = 0; sp < DSPLIT; sp++) {
            C += g_cos_part[((size_t)sp * N_RES + n) * BATCH + lane];
            S += g_sin_part[((size_t)sp * N_RES + n) * BATCH + lane];
        }
        float st, ct;
        __sincosf(__ldg(t + lane), &st, &ct);
        g_cosT[(size_t)n * BATCH + lane] = fmaf(C, ct, -S * st);
        g_sinT[(size_t)n * BATCH + lane] = fmaf(S, ct,  C * st);
        if (threadIdx.x == 0) g_cnt_res[blockIdx.x] = 0;
    }
}

// ---------------------------------------------------------------------------
// K3: output projection. grid (64, NSPLIT=4, 2). Pipelined like proj.
// Last split-block combines + silu + transposed store.
// ---------------------------------------------------------------------------
__global__ void __launch_bounds__(256)
outproj_kernel(const float* __restrict__ wr,
               const float* __restrict__ wi,
               float* __restrict__ out) {
    __shared__ float sbuf[NSTAGE][TILE_G * GCHUNK];   // 24 KB
    __shared__ float red[8][TILE_G][32];              // 16 KB
    __shared__ float tile[TILE_G][33];                // 2 KB
    __shared__ int   s_last;

    const int  dt      = blockIdx.x * TILE_G;
    const int  nbase   = blockIdx.y * RRANGE;
    const bool is_imag = blockIdx.z != 0;
    const int  w       = threadIdx.x >> 5;
    const int  lane    = threadIdx.x & 31;

    const float* wbase = is_imag ? wi : wr;
    const float* src   = is_imag ? g_sinT : g_cosT;

    float acc[TILE_G];
    #pragma unroll
    for (int i = 0; i < TILE_G; i++) acc[i] = 0.f;

    gemm_pipeline(wbase + (size_t)dt * N_RES, N_RES, nbase, src,
                  sbuf, acc, w, lane, threadIdx.x);

    #pragma unroll
    for (int i = 0; i < TILE_G; i++) red[w][i][lane] = acc[i];
    __syncthreads();

    #pragma unroll
    for (int p = 0; p < 2; p++) {
        int td  = (threadIdx.x >> 5) + p * 8;
        int row = (is_imag ? D_MODEL : 0) + dt + td;
        float s = 0.f;
        #pragma unroll
        for (int ww = 0; ww < 8; ww++) s += red[ww][td][lane];
        g_out_part[((size_t)blockIdx.y * 2 * D_MODEL + row) * BATCH + lane] = s;
    }

    const int cidx = blockIdx.z * (D_MODEL / TILE_G) + blockIdx.x;
    __threadfence();
    if (threadIdx.x == 0) {
        int old = atomicAdd(&g_cnt_out[cidx], 1);
        s_last = (old == NSPLIT - 1);
    }
    __syncthreads();
    if (s_last) {
        __threadfence();
        #pragma unroll
        for (int p = 0; p < 2; p++) {
            int td  = (threadIdx.x >> 5) + p * 8;
            int row = (is_imag ? D_MODEL : 0) + dt + td;
            float c = 0.f;
            #pragma unroll
            for (int sp = 0; sp < NSPLIT; sp++)
                c += g_out_part[((size_t)sp * 2 * D_MODEL + row) * BATCH + lane];
            tile[td][lane] = c / (1.0f + __expf(-c));
        }
        __syncthreads();
        #pragma unroll
        for (int p = 0; p < 2; p++) {
            const int b  = threadIdx.x >> 3;
            const int dl = (threadIdx.x & 7) + p * 8;
            out[(is_imag ? BATCH * D_MODEL : 0) + (size_t)b * D_MODEL + dt + dl] = tile[dl][b];
        }
        if (threadIdx.x == 0) g_cnt_out[cidx] = 0;
    }
}

// ---------------------------------------------------------------------------
extern "C" void kernel_launch(void* const* d_in, const int* in_sizes, int n_in,
                              void* d_out, int out_size) {
    const float* x_real = (const float*)d_in[0];
    const float* x_imag = (const float*)d_in[1];
    const float* t      = (const float*)d_in[2];
    const float* ipw    = (const float*)d_in[3];
    const float* ipb    = (const float*)d_in[4];
    const float* W      = (const float*)d_in[5];
    const float* Bmat   = (const float*)d_in[6];
    const float* orw    = (const float*)d_in[7];
    const float* oiw    = (const float*)d_in[8];
    float* out = (float*)d_out;

    prep_kernel<<<64, 256>>>(x_real, x_imag);
    proj_kernel<<<dim3(D_MODEL / TILE_G, KSPLIT), 256>>>(ipw, ipb);
    resonance_kernel<<<dim3(N_RES / 8, DSPLIT), 256>>>(W, Bmat, t);
    outproj_kernel<<<dim3(D_MODEL / TILE_G, NSPLIT, 2), 256>>>(orw, oiw, out);
}